// round 16
// baseline (speedup 1.0000x reference)
#include <cuda_runtime.h>
#include <cuda_fp16.h>
#include <math.h>
#include <stdint.h>

#define EMBED 1024
#define HEADS 16
#define HDIM  64
#define BATCH 4
#define SEQ   2048
#define MTOT  (BATCH * SEQ)   /* 8192 */

#define BKC     32            /* GEMM K floats per chunk (2 x k16 mma) */
#define NCHUNK  (EMBED / BKC) /* 32 */
#define SSTRW   20            /* GEMM smem row stride in 32-bit words */

// ---- scratch (device globals; no allocations allowed) ----
__device__ float g_Q[BATCH * HEADS * SEQ * HDIM];  // [B][H][N][Dh]
__device__ float g_K[BATCH * HEADS * SEQ * HDIM];
__device__ float g_V[BATCH * HEADS * SEQ * HDIM];
__device__ float g_C[MTOT * EMBED];                // attention ctx, [B][N][D]

// pack two floats -> f16x2 (round-to-nearest; .x = lo)
__device__ __forceinline__ uint32_t h2(float lo, float hi) {
    __half2 h = __floats2half2_rn(lo, hi);
    return *(uint32_t*)&h;
}

// D += A(16x16) * B(16x8), f16 inputs, f32 accum
__device__ __forceinline__ void mma_f16(float* d, const uint32_t* a, const uint32_t* b) {
    asm volatile(
        "mma.sync.aligned.m16n8k16.row.col.f32.f16.f16.f32 "
        "{%0,%1,%2,%3}, {%4,%5,%6,%7}, {%8,%9}, {%0,%1,%2,%3};"
        : "+f"(d[0]), "+f"(d[1]), "+f"(d[2]), "+f"(d[3])
        : "r"(a[0]), "r"(a[1]), "r"(a[2]), "r"(a[3]),
          "r"(b[0]), "r"(b[1]));
}

__device__ __forceinline__ void ldsm_x4(uint32_t& r0, uint32_t& r1,
                                        uint32_t& r2, uint32_t& r3,
                                        uint32_t addr) {
    asm volatile("ldmatrix.sync.aligned.m8n8.x4.shared.b16 {%0,%1,%2,%3}, [%4];"
                 : "=r"(r0), "=r"(r1), "=r"(r2), "=r"(r3) : "r"(addr));
}

// ============================================================================
// Round-10 GEMM mainloop (verbatim): BM=BN=128, BK=32 floats, 256 threads,
// double-buffered smem, register prefetch with f32->f16 conversion at store,
// ldmatrix fragments.
// ============================================================================
__device__ __forceinline__ void gemm_main(const float* __restrict__ Asrc,
                                          const float* __restrict__ Bw,
                                          int bm, int bn,
                                          float (&acc)[4][4][4])
{
    __shared__ uint32_t sA[2][128 * SSTRW];
    __shared__ uint32_t sB[2][128 * SSTRW];

    const int tid  = threadIdx.x;
    const int wid  = tid >> 5;
    const int lane = tid & 31;
    const int warp_m = (wid & 1) * 64;
    const int warp_n = (wid >> 1) * 32;

    const int qrow = tid >> 3;
    const int qcol = (tid & 7) << 2;
    const int wcol = qcol >> 1;

    const int arow = ((lane >> 3) & 1) * 8 + (lane & 7);
    const int acol = (lane >> 4) << 2;
    const uint32_t aoff = ((warp_m + arow) * SSTRW + acol) * 4;
    const int brow = ((lane >> 4) & 1) * 8 + (lane & 7);
    const int bcol = ((lane >> 3) & 1) << 2;
    const uint32_t boff = ((warp_n + brow) * SSTRW + bcol) * 4;

    const uint32_t sAb[2] = { (uint32_t)__cvta_generic_to_shared(&sA[0][0]),
                              (uint32_t)__cvta_generic_to_shared(&sA[1][0]) };
    const uint32_t sBb[2] = { (uint32_t)__cvta_generic_to_shared(&sB[0][0]),
                              (uint32_t)__cvta_generic_to_shared(&sB[1][0]) };

    uint2 pA[4], pB[4];

#define LOADPF(cc) do { int ko = (cc) * BKC + qcol; \
    _Pragma("unroll") \
    for (int q = 0; q < 4; q++) { \
        float4 a = *(const float4*)(Asrc + (bm + qrow + q * 32) * EMBED + ko); \
        float4 b = *(const float4*)(Bw   + (bn + qrow + q * 32) * EMBED + ko); \
        pA[q].x = h2(a.x, a.y); pA[q].y = h2(a.z, a.w); \
        pB[q].x = h2(b.x, b.y); pB[q].y = h2(b.z, b.w); \
    } } while (0)

#define STOREPF(buf) do { \
    _Pragma("unroll") \
    for (int q = 0; q < 4; q++) { \
        *(uint2*)&sA[buf][(qrow + q * 32) * SSTRW + wcol] = pA[q]; \
        *(uint2*)&sB[buf][(qrow + q * 32) * SSTRW + wcol] = pB[q]; \
    } } while (0)

    LOADPF(0);
    STOREPF(0);
    LOADPF(1);

    for (int c = 0; c < NCHUNK; c++) {
        __syncthreads();
        if (c + 1 < NCHUNK) {
            STOREPF((c + 1) & 1);
            if (c + 2 < NCHUNK) LOADPF(c + 2);
        }
        const uint32_t cAa = sAb[c & 1] + aoff;
        const uint32_t cBa = sBb[c & 1] + boff;

#pragma unroll
        for (int ks = 0; ks < 2; ks++) {
            const uint32_t kbb = ks * 8 * 4;
            uint32_t af[4][4], bf[4][2];
#pragma unroll
            for (int i = 0; i < 4; i++)
                ldsm_x4(af[i][0], af[i][1], af[i][2], af[i][3],
                        cAa + i * 16 * SSTRW * 4 + kbb);
#pragma unroll
            for (int jp = 0; jp < 2; jp++)
                ldsm_x4(bf[2 * jp][0], bf[2 * jp][1],
                        bf[2 * jp + 1][0], bf[2 * jp + 1][1],
                        cBa + jp * 16 * SSTRW * 4 + kbb);
#pragma unroll
            for (int i = 0; i < 4; i++)
#pragma unroll
                for (int j = 0; j < 4; j++)
                    mma_f16(acc[i][j], af[i], bf[j]);
        }
    }
#undef LOADPF
#undef STOREPF
}

// ============================================================================
// Fused QKV projection (round-10 verbatim)
// ============================================================================
__global__ void __launch_bounds__(256, 2)
qkv_gemm(const float* __restrict__ x,
         const float* __restrict__ Wq, const float* __restrict__ Wk,
         const float* __restrict__ Wv,
         const float* __restrict__ bq, const float* __restrict__ bk,
         const float* __restrict__ bv)
{
    const int z = blockIdx.z;
    const float* Bw   = (z == 0) ? Wq : (z == 1) ? Wk : Wv;
    const float* bias = (z == 0) ? bq : (z == 1) ? bk : bv;
    float* C          = (z == 0) ? g_Q : (z == 1) ? g_K : g_V;

    const int bm = blockIdx.x * 128;
    const int bn = blockIdx.y * 128;

    float acc[4][4][4];
#pragma unroll
    for (int i = 0; i < 4; i++)
#pragma unroll
        for (int j = 0; j < 4; j++)
#pragma unroll
            for (int r = 0; r < 4; r++) acc[i][j][r] = 0.f;

    gemm_main(x, Bw, bm, bn, acc);

    const int tid  = threadIdx.x;
    const int wid  = tid >> 5;
    const int lane = tid & 31;
    const int lr4  = lane >> 2;
    const int lc4  = lane & 3;
    const int warp_m = (wid & 1) * 64;
    const int warp_n = (wid >> 1) * 32;

#pragma unroll
    for (int i = 0; i < 4; i++) {
#pragma unroll
        for (int j = 0; j < 4; j++) {
            int row0 = bm + warp_m + i * 16 + lr4;
            int col0 = bn + warp_n + j * 8 + 2 * lc4;
#pragma unroll
            for (int half = 0; half < 2; half++) {
                int row = row0 + half * 8;
                float2 o;
                o.x = acc[i][j][half * 2 + 0] + __ldg(bias + col0 + 0);
                o.y = acc[i][j][half * 2 + 1] + __ldg(bias + col0 + 1);
                int b   = row >> 11;
                int tok = row & 2047;
                int h   = col0 >> 6;
                int dh  = col0 & 63;
                *(float2*)&C[(((b << 4) + h) * SEQ + tok) * HDIM + dh] = o;
            }
        }
    }
}

// ============================================================================
// Output projection, 128x64 tiles: same instruction patterns as gemm_main but
// B-side halved (64 rows, 1 ldsm_x4/k-step, warp n-tile = 16 cols).
// Grid 1024 blocks (3.46 waves) vs round-10's 512 (1.73 waves) -> tail halved.
// Per-output accumulation order identical -> bit-identical numerics.
// ============================================================================
__global__ void __launch_bounds__(256, 2)
out_gemm_n64(const float* __restrict__ Wo, float* __restrict__ out)
{
    __shared__ uint32_t sA[2][128 * SSTRW];
    __shared__ uint32_t sB[2][64 * SSTRW];

    const int tid  = threadIdx.x;
    const int wid  = tid >> 5;
    const int lane = tid & 31;
    const int warp_m = (wid & 1) * 64;
    const int warp_n = (wid >> 1) * 16;

    const int bm = blockIdx.x * 128;
    const int bn = blockIdx.y * 64;

    const int qrow = tid >> 3;
    const int qcol = (tid & 7) << 2;
    const int wcol = qcol >> 1;

    const int arow = ((lane >> 3) & 1) * 8 + (lane & 7);
    const int acol = (lane >> 4) << 2;
    const uint32_t aoff = ((warp_m + arow) * SSTRW + acol) * 4;
    const int brow = ((lane >> 4) & 1) * 8 + (lane & 7);
    const int bcol = ((lane >> 3) & 1) << 2;
    const uint32_t boff = ((warp_n + brow) * SSTRW + bcol) * 4;

    const uint32_t sAb[2] = { (uint32_t)__cvta_generic_to_shared(&sA[0][0]),
                              (uint32_t)__cvta_generic_to_shared(&sA[1][0]) };
    const uint32_t sBb[2] = { (uint32_t)__cvta_generic_to_shared(&sB[0][0]),
                              (uint32_t)__cvta_generic_to_shared(&sB[1][0]) };

    float acc[4][2][4];
#pragma unroll
    for (int i = 0; i < 4; i++)
#pragma unroll
        for (int j = 0; j < 2; j++)
#pragma unroll
            for (int r = 0; r < 4; r++) acc[i][j][r] = 0.f;

    uint2 pA[4], pB[2];

#define LOADPF(cc) do { int ko = (cc) * BKC + qcol; \
    _Pragma("unroll") \
    for (int q = 0; q < 4; q++) { \
        float4 a = *(const float4*)(g_C + (bm + qrow + q * 32) * EMBED + ko); \
        pA[q].x = h2(a.x, a.y); pA[q].y = h2(a.z, a.w); \
    } \
    _Pragma("unroll") \
    for (int q = 0; q < 2; q++) { \
        float4 b = *(const float4*)(Wo + (bn + qrow + q * 32) * EMBED + ko); \
        pB[q].x = h2(b.x, b.y); pB[q].y = h2(b.z, b.w); \
    } } while (0)

#define STOREPF(buf) do { \
    _Pragma("unroll") \
    for (int q = 0; q < 4; q++) \
        *(uint2*)&sA[buf][(qrow + q * 32) * SSTRW + wcol] = pA[q]; \
    _Pragma("unroll") \
    for (int q = 0; q < 2; q++) \
        *(uint2*)&sB[buf][(qrow + q * 32) * SSTRW + wcol] = pB[q]; \
    } while (0)

    LOADPF(0);
    STOREPF(0);
    LOADPF(1);

    for (int c = 0; c < NCHUNK; c++) {
        __syncthreads();
        if (c + 1 < NCHUNK) {
            STOREPF((c + 1) & 1);
            if (c + 2 < NCHUNK) LOADPF(c + 2);
        }
        const uint32_t cAa = sAb[c & 1] + aoff;
        const uint32_t cBa = sBb[c & 1] + boff;

#pragma unroll
        for (int ks = 0; ks < 2; ks++) {
            const uint32_t kbb = ks * 8 * 4;
            uint32_t af[4][4], bf[2][2];
#pragma unroll
            for (int i = 0; i < 4; i++)
                ldsm_x4(af[i][0], af[i][1], af[i][2], af[i][3],
                        cAa + i * 16 * SSTRW * 4 + kbb);
            ldsm_x4(bf[0][0], bf[0][1], bf[1][0], bf[1][1], cBa + kbb);
#pragma unroll
            for (int i = 0; i < 4; i++)
#pragma unroll
                for (int j = 0; j < 2; j++)
                    mma_f16(acc[i][j], af[i], bf[j]);
        }
    }
#undef LOADPF
#undef STOREPF

    const int lr4 = lane >> 2;
    const int lc4 = lane & 3;
#pragma unroll
    for (int i = 0; i < 4; i++) {
#pragma unroll
        for (int j = 0; j < 2; j++) {
            int row0 = bm + warp_m + i * 16 + lr4;
            int col0 = bn + warp_n + j * 8 + 2 * lc4;
#pragma unroll
            for (int half = 0; half < 2; half++) {
                int row = row0 + half * 8;
                float2 o;
                o.x = acc[i][j][half * 2 + 0];
                o.y = acc[i][j][half * 2 + 1];
                *(float2*)&out[row * EMBED + col0] = o;
            }
        }
    }
}

// ============================================================================
// Flash attention (round-10 verbatim): fp16 mma + ldmatrix, BQ=128,
// 8 warps x 16 q-rows, Q in registers, double-buffered sK/sVt, 1 sync/tile.
// ============================================================================
__global__ void __launch_bounds__(256, 2)
attn_mma()
{
    __shared__ uint32_t sK [2][64 * 32];
    __shared__ uint32_t sVt[2][64 * 32];

    const int tid  = threadIdx.x;
    const int wid  = tid >> 5;
    const int lane = tid & 31;
    const int lr4  = lane >> 2;
    const int lc4  = lane & 3;
    const int warp_m = wid * 16;
    const int q0 = blockIdx.x * 128;
    const int h  = blockIdx.y;
    const int b  = blockIdx.z;

    const float* Qb = g_Q + ((b * HEADS + h) * SEQ + q0) * HDIM;
    const float* Kb = g_K + ((b * HEADS + h) * SEQ) * HDIM;
    const float* Vb = g_V + ((b * HEADS + h) * SEQ) * HDIM;

    const int kwc = (tid & 15) << 1;

    const int lrow = ((lane >> 4) & 1) * 8 + (lane & 7);
    const int lcol = ((lane >> 3) & 1) << 2;
    const int xorv = (lane & 7) << 2;

    const uint32_t sKb[2] = { (uint32_t)__cvta_generic_to_shared(&sK[0][0]),
                              (uint32_t)__cvta_generic_to_shared(&sK[1][0]) };
    const uint32_t sVb[2] = { (uint32_t)__cvta_generic_to_shared(&sVt[0][0]),
                              (uint32_t)__cvta_generic_to_shared(&sVt[1][0]) };

    uint32_t qf[4][4];
    {
        const float* qr0 = Qb + (warp_m + lr4) * HDIM;
        const float* qr1 = qr0 + 8 * HDIM;
#pragma unroll
        for (int ks = 0; ks < 4; ks++) {
            int c = ks * 16 + 2 * lc4;
            qf[ks][0] = h2(qr0[c    ] * 0.125f, qr0[c + 1] * 0.125f);
            qf[ks][1] = h2(qr1[c    ] * 0.125f, qr1[c + 1] * 0.125f);
            qf[ks][2] = h2(qr0[c + 8] * 0.125f, qr0[c + 9] * 0.125f);
            qf[ks][3] = h2(qr1[c + 8] * 0.125f, qr1[c + 9] * 0.125f);
        }
    }

    uint2    pk[4];
    uint32_t pv[2][4];

#define LOADKV(tt) do { const int kv0 = (tt) * 64; \
    _Pragma("unroll") \
    for (int r = 0; r < 4; r++) { \
        int idx = tid + r * 256; \
        int row = idx >> 4; \
        float4 kv = *(const float4*)&Kb[(kv0 + row) * HDIM + (kwc << 1)]; \
        pk[r].x = h2(kv.x, kv.y); pk[r].y = h2(kv.z, kv.w); \
    } \
    _Pragma("unroll") \
    for (int r = 0; r < 2; r++) { \
        int t2  = tid + r * 256; \
        int kv2 = t2 >> 4; \
        int d4  = (t2 & 15) << 2; \
        float4 v0 = *(const float4*)&Vb[(kv0 + 2 * kv2    ) * HDIM + d4]; \
        float4 v1 = *(const float4*)&Vb[(kv0 + 2 * kv2 + 1) * HDIM + d4]; \
        pv[r][0] = h2(v0.x, v1.x); pv[r][1] = h2(v0.y, v1.y); \
        pv[r][2] = h2(v0.z, v1.z); pv[r][3] = h2(v0.w, v1.w); \
    } } while (0)

#define STOREKV(buf) do { \
    _Pragma("unroll") \
    for (int r = 0; r < 4; r++) { \
        int idx = tid + r * 256; \
        int row = idx >> 4; \
        *(uint2*)&sK[buf][row * 32 + (kwc ^ ((row & 7) << 2))] = pk[r]; \
    } \
    _Pragma("unroll") \
    for (int r = 0; r < 2; r++) { \
        int t2  = tid + r * 256; \
        int kv2 = t2 >> 4; \
        int d4  = (t2 & 15) << 2; \
        sVt[buf][(d4 + 0) * 32 + (kv2 ^ (((d4 + 0) & 7) << 2))] = pv[r][0]; \
        sVt[buf][(d4 + 1) * 32 + (kv2 ^ (((d4 + 1) & 7) << 2))] = pv[r][1]; \
        sVt[buf][(d4 + 2) * 32 + (kv2 ^ (((d4 + 2) & 7) << 2))] = pv[r][2]; \
        sVt[buf][(d4 + 3) * 32 + (kv2 ^ (((d4 + 3) & 7) << 2))] = pv[r][3]; \
    } } while (0)

    float out[8][4];
#pragma unroll
    for (int n = 0; n < 8; n++)
#pragma unroll
        for (int c = 0; c < 4; c++) out[n][c] = 0.f;
    float m0 = -INFINITY, m1 = -INFINITY, l0 = 0.f, l1 = 0.f;

    const int NT = SEQ / 64;
    LOADKV(0);
    STOREKV(0);
    LOADKV(1);

    for (int t = 0; t < NT; t++) {
        __syncthreads();
        if (t + 1 < NT) {
            STOREKV((t + 1) & 1);
            if (t + 2 < NT) LOADKV(t + 2);
        }
        const uint32_t cKa = sKb[t & 1];
        const uint32_t cVa = sVb[t & 1];

        float s[8][4];
#pragma unroll
        for (int j = 0; j < 8; j++)
#pragma unroll
            for (int c = 0; c < 4; c++) s[j][c] = 0.f;

#pragma unroll
        for (int ks = 0; ks < 4; ks++) {
            const int colk = (ks * 8 + lcol) ^ xorv;
#pragma unroll
            for (int jp = 0; jp < 4; jp++) {
                uint32_t bf[4];
                ldsm_x4(bf[0], bf[1], bf[2], bf[3],
                        cKa + ((jp * 16 + lrow) * 32 + colk) * 4);
                mma_f16(s[2 * jp    ], qf[ks], bf);
                mma_f16(s[2 * jp + 1], qf[ks], bf + 2);
            }
        }

        float mx0 = -INFINITY, mx1 = -INFINITY;
#pragma unroll
        for (int j = 0; j < 8; j++) {
            mx0 = fmaxf(mx0, fmaxf(s[j][0], s[j][1]));
            mx1 = fmaxf(mx1, fmaxf(s[j][2], s[j][3]));
        }
        mx0 = fmaxf(mx0, __shfl_xor_sync(0xffffffffu, mx0, 1));
        mx0 = fmaxf(mx0, __shfl_xor_sync(0xffffffffu, mx0, 2));
        mx1 = fmaxf(mx1, __shfl_xor_sync(0xffffffffu, mx1, 1));
        mx1 = fmaxf(mx1, __shfl_xor_sync(0xffffffffu, mx1, 2));
        float mn0 = fmaxf(m0, mx0), mn1 = fmaxf(m1, mx1);
        float rs0 = __expf(m0 - mn0), rs1 = __expf(m1 - mn1);
        m0 = mn0; m1 = mn1;
        float sum0 = 0.f, sum1 = 0.f;
#pragma unroll
        for (int j = 0; j < 8; j++) {
            s[j][0] = __expf(s[j][0] - mn0);
            s[j][1] = __expf(s[j][1] - mn0);
            sum0 += s[j][0] + s[j][1];
            s[j][2] = __expf(s[j][2] - mn1);
            s[j][3] = __expf(s[j][3] - mn1);
            sum1 += s[j][2] + s[j][3];
        }
        sum0 += __shfl_xor_sync(0xffffffffu, sum0, 1);
        sum0 += __shfl_xor_sync(0xffffffffu, sum0, 2);
        sum1 += __shfl_xor_sync(0xffffffffu, sum1, 1);
        sum1 += __shfl_xor_sync(0xffffffffu, sum1, 2);
        l0 = l0 * rs0 + sum0;
        l1 = l1 * rs1 + sum1;
#pragma unroll
        for (int n = 0; n < 8; n++) {
            out[n][0] *= rs0; out[n][1] *= rs0;
            out[n][2] *= rs1; out[n][3] *= rs1;
        }

#pragma unroll
        for (int jp = 0; jp < 4; jp++) {
            uint32_t a[4];
            a[0] = h2(s[2 * jp    ][0], s[2 * jp    ][1]);
            a[1] = h2(s[2 * jp    ][2], s[2 * jp    ][3]);
            a[2] = h2(s[2 * jp + 1][0], s[2 * jp + 1][1]);
            a[3] = h2(s[2 * jp + 1][2], s[2 * jp + 1][3]);
            const int colv = (jp * 8 + lcol) ^ xorv;
#pragma unroll
            for (int np = 0; np < 4; np++) {
                uint32_t bf[4];
                ldsm_x4(bf[0], bf[1], bf[2], bf[3],
                        cVa + ((np * 16 + lrow) * 32 + colv) * 4);
                mma_f16(out[2 * np    ], a, bf);
                mma_f16(out[2 * np + 1], a, bf + 2);
            }
        }
    }
#undef LOADKV
#undef STOREKV

    const float inv0 = 1.f / l0, inv1 = 1.f / l1;
    float* Cb = g_C + (b * SEQ + q0) * EMBED + h * HDIM;
    const int r0 = warp_m + lr4, r1 = r0 + 8;
#pragma unroll
    for (int n = 0; n < 8; n++) {
        int col = n * 8 + 2 * lc4;
        float2 o;
        o.x = out[n][0] * inv0; o.y = out[n][1] * inv0;
        *(float2*)&Cb[r0 * EMBED + col] = o;
        o.x = out[n][2] * inv1; o.y = out[n][3] * inv1;
        *(float2*)&Cb[r1 * EMBED + col] = o;
    }
}

// ============================================================================
extern "C" void kernel_launch(void* const* d_in, const int* in_sizes, int n_in,
                              void* d_out, int out_size)
{
    (void)in_sizes; (void)n_in; (void)out_size;
    const float* x  = (const float*)d_in[0];
    const float* Wq = (const float*)d_in[1];
    const float* bq = (const float*)d_in[2];
    const float* Wk = (const float*)d_in[3];
    const float* bk = (const float*)d_in[4];
    const float* Wv = (const float*)d_in[5];
    const float* bv = (const float*)d_in[6];
    const float* Wo = (const float*)d_in[7];
    float* out = (float*)d_out;

    qkv_gemm<<<dim3(MTOT / 128, EMBED / 128, 3), 256>>>(x, Wq, Wk, Wv, bq, bk, bv);

    attn_mma<<<dim3(SEQ / 128, HEADS, BATCH), 256>>>();

    out_gemm_n64<<<dim3(MTOT / 128, EMBED / 64), 256>>>(Wo, out);
}